// round 12
// baseline (speedup 1.0000x reference)
#include <cuda_runtime.h>
#include <cuda_fp16.h>
#include <cstdint>

#define IC1 10
#define OC1 64
#define OC2 128
#define NB  64          // 2 images x 32 batch
#define M0  0.10f       // pre-BN ambiguity margin for fp16 accumulation

__device__ int      g_cnt[NB][OC1][9];   // S, Rf, Rl, Cf, Cl, q_tl, q_tr, q_bl, q_br
__device__ float    g_s2[NB][OC2];
__device__ float    g_inv1[OC1],  g_beta1[OC1];
__device__ float    g_inv2[OC2],  g_beta2[OC2];
__device__ __align__(16) uint32_t g_Wd[90 * 64];  // dup half2 (w,w), [r][oc]

// dynamic smem layout (bytes)
#define SM_W    0        // u32[90*64] = 23040
#define SM_IN   23040    // float[6120] = 24480
#define SM_SPK  47520    // uchar[64*128] = 8192
#define SM_SC   55712    // unused pad
#define SM_LC   56992    // int[4]
#define SM_LIST 57008    // u16[8192] = 16384 (worst-case exact capacity)
#define SMEM_BYTES 73392

// ---------------------------------------------------------------------------
// prep: zero counters, fold BN params, build duplicated-half2 weight table
// ---------------------------------------------------------------------------
__global__ void prep_kernel(const float* __restrict__ w1,
                            const float* __restrict__ g1, const float* __restrict__ b1,
                            const float* __restrict__ m1, const float* __restrict__ v1,
                            const float* __restrict__ g2, const float* __restrict__ b2,
                            const float* __restrict__ m2, const float* __restrict__ v2) {
    int gid = blockIdx.x * blockDim.x + threadIdx.x;
    int* c = &g_cnt[0][0][0];
    for (int i = gid; i < NB * OC1 * 9; i += gridDim.x * blockDim.x) c[i] = 0;
    if (blockIdx.x == 0) {
        int t = threadIdx.x;
        if (t < OC1) {
            float inv = g1[t] / sqrtf(v1[t] + 1e-5f);
            g_inv1[t] = inv;
            g_beta1[t] = b1[t] - m1[t] * inv;
        }
        if (t < OC2) {
            float inv = g2[t] / sqrtf(v2[t] + 1e-5f);
            g_inv2[t] = inv;
            g_beta2[t] = b2[t] - m2[t] * inv;
        }
    }
    if (gid < 90 * 64) {
        int r = gid >> 6, oc = gid & 63;
        __half h = __float2half_rn(__ldg(&w1[oc * 90 + r]));
        __half2 d = __halves2half2(h, h);
        g_Wd[r * 64 + oc] = *reinterpret_cast<uint32_t*>(&d);
    }
}

// ---------------------------------------------------------------------------
// stage A: conv1 via HFMA2 (oc pairs dup-weight x position-pair inputs)
//          + BN + maxpool2 + margin-certified spike + exact in-block fixup
// grid (8, 16, 64), block 128. Thread = one pooled window for all 64 oc.
// ---------------------------------------------------------------------------
__global__ __launch_bounds__(128, 2) void stageA_kernel(const float* __restrict__ x0,
                                                        const float* __restrict__ x1,
                                                        const float* __restrict__ w1) {
    extern __shared__ char smem[];
    uint32_t*      s_w   = (uint32_t*)(smem + SM_W);
    float*         s_in  = (float*)(smem + SM_IN);
    unsigned char* spk   = (unsigned char*)(smem + SM_SPK);
    int*           sLC   = (int*)(smem + SM_LC);
    uint16_t*      sList = (uint16_t*)(smem + SM_LIST);

    const int tid = threadIdx.x;
    const int bx = blockIdx.x, by = blockIdx.y, n = blockIdx.z;
    const float* __restrict__ x = (n < 32) ? x0 : x1;
    const int b = n & 31;

    // load dup-weight table (5760 u32 = 1440 uint4)
    {
        const uint4* gw = (const uint4*)g_Wd;
        uint4* sw4 = (uint4*)s_w;
        for (int i = tid; i < 1440; i += 128) sw4[i] = __ldg(&gw[i]);
    }
    if (tid == 0) sLC[0] = 0;

    // stage input tile fp32 (18 x 34 per ic), SAME zero padding
    const int iy0 = by * 16 - 1;
    const int ix0 = bx * 32 - 1;
    for (int i = tid; i < IC1 * 612; i += 128) {
        int ic = i / 612, r2 = i % 612;
        int rw = r2 / 34, cl = r2 % 34;
        int gy = iy0 + rw, gx = ix0 + cl;
        float v = 0.f;
        if ((unsigned)gy < 256u && (unsigned)gx < 256u)
            v = __ldg(&x[((b * IC1 + ic) * 256 + gy) * 256 + gx]);
        s_in[i] = v;
    }
    __syncthreads();

    const int lpx = tid & 15, lpy = tid >> 4;
    const int rr = 2 * lpy, cc = 2 * lpx;

    // pack overlapping input pairs once: hp[ic][row 0..3][kx 0..2] = (v[kx], v[kx+1])
    uint32_t hp[IC1 * 12];
#pragma unroll
    for (int ic = 0; ic < IC1; ++ic) {
        float r[4][4];
#pragma unroll
        for (int i = 0; i < 4; ++i) {
            const float2* p = (const float2*)&s_in[ic * 612 + (rr + i) * 34 + cc];
            float2 u = p[0], w = p[1];
            r[i][0] = u.x; r[i][1] = u.y; r[i][2] = w.x; r[i][3] = w.y;
        }
#pragma unroll
        for (int i = 0; i < 4; ++i)
#pragma unroll
            for (int kx = 0; kx < 3; ++kx) {
                __half2 h = __floats2half2_rn(r[i][kx], r[i][kx + 1]);
                hp[ic * 12 + i * 3 + kx] = *reinterpret_cast<uint32_t*>(&h);
            }
    }

    // oc-group sweep: 8 oc per g, HFMA2 accumulate (fp16)
#pragma unroll 1
    for (int g = 0; g < 8; ++g) {
        __half2 accA[8], accB[8];   // A: pool row y0 (x0,x1); B: row y1
#pragma unroll
        for (int o = 0; o < 8; ++o) {
            accA[o] = __half2half2(__ushort_as_half(0));
            accB[o] = __half2half2(__ushort_as_half(0));
        }
#pragma unroll
        for (int ic = 0; ic < IC1; ++ic) {
#pragma unroll
            for (int k = 0; k < 9; ++k) {
                const int ky = k / 3, kx = k % 3;
                uint4 wa = *(const uint4*)&s_w[(ic * 9 + k) * 64 + g * 8];
                uint4 wb = *(const uint4*)&s_w[(ic * 9 + k) * 64 + g * 8 + 4];
                uint32_t wq[8] = {wa.x, wa.y, wa.z, wa.w, wb.x, wb.y, wb.z, wb.w};
                __half2 hA = *reinterpret_cast<__half2*>(&hp[ic * 12 + ky * 3 + kx]);
                __half2 hB = *reinterpret_cast<__half2*>(&hp[ic * 12 + (ky + 1) * 3 + kx]);
#pragma unroll
                for (int o = 0; o < 8; ++o) {
                    __half2 w = *reinterpret_cast<__half2*>(&wq[o]);
                    accA[o] = __hfma2(w, hA, accA[o]);
                    accB[o] = __hfma2(w, hB, accB[o]);
                }
            }
        }
        // epilogue: BN + pool max + margin classify
#pragma unroll
        for (int o = 0; o < 8; ++o) {
            const int oc = g * 8 + o;
            float2 a01 = __half22float2(accA[o]);
            float2 a23 = __half22float2(accB[o]);
            float mx = fmaxf(fmaxf(a01.x, a01.y), fmaxf(a23.x, a23.y));
            float mn = fminf(fminf(a01.x, a01.y), fminf(a23.x, a23.y));
            float inv = __ldg(&g_inv1[oc]);
            float bet = __ldg(&g_beta1[oc]);
            float zb = (inv >= 0.f ? mx : mn) * inv + bet;
            float Mz = M0 * fabsf(inv);
            unsigned char s = 0;
            if (zb - Mz > 1.0f) s = 1;
            else if (zb + Mz > 1.0f) {
                int ix = atomicAdd(&sLC[0], 1);
                sList[ix] = (uint16_t)(tid * 64 + oc);
            }
            spk[oc * 128 + tid] = s;
        }
    }
    __syncthreads();

    // exact fp32 fixup of ambiguous windows from the staged fp32 tile
    {
        const int cnt = sLC[0];
        for (int i = tid; i < cnt; i += 128) {
            const int e = sList[i];
            const int q = e >> 6, oc = e & 63;
            const int r0 = 2 * (q >> 4), c0 = 2 * (q & 15);
            float a0 = 0.f, a1 = 0.f, a2 = 0.f, a3 = 0.f;
#pragma unroll 1
            for (int ic = 0; ic < IC1; ++ic) {
                float v[4][4];
#pragma unroll
                for (int iy = 0; iy < 4; ++iy)
#pragma unroll
                    for (int ixx = 0; ixx < 4; ++ixx)
                        v[iy][ixx] = s_in[ic * 612 + (r0 + iy) * 34 + (c0 + ixx)];
                const float* wr = w1 + oc * 90 + ic * 9;
#pragma unroll
                for (int ky = 0; ky < 3; ++ky)
#pragma unroll
                    for (int kx = 0; kx < 3; ++kx) {
                        float wv = __ldg(&wr[ky * 3 + kx]);
                        a0 = fmaf(wv, v[ky][kx],         a0);
                        a1 = fmaf(wv, v[ky][kx + 1],     a1);
                        a2 = fmaf(wv, v[ky + 1][kx],     a2);
                        a3 = fmaf(wv, v[ky + 1][kx + 1], a3);
                    }
            }
            const float inv = __ldg(&g_inv1[oc]), bet = __ldg(&g_beta1[oc]);
            float zm = fmaxf(fmaxf(fmaf(a0, inv, bet), fmaf(a1, inv, bet)),
                             fmaxf(fmaf(a2, inv, bet), fmaf(a3, inv, bet)));
            spk[oc * 128 + q] = (zm > 1.0f);
        }
    }
    __syncthreads();

    // reduce spike map -> the 9 aggregates
    if (tid < 64) {
        const int oc = tid;
        const int* row = (const int*)&spk[oc * 128];
        int S = 0;
#pragma unroll
        for (int j = 0; j < 32; ++j) S = __dp4a(row[j], 0x01010101, S);
        if (S) atomicAdd(&g_cnt[n][oc][0], S);
        if (by == 0) {      // pooled row 0 lives at lpy==0 -> q 0..15
            int Rf = 0;
#pragma unroll
            for (int j = 0; j < 4; ++j) Rf = __dp4a(row[j], 0x01010101, Rf);
            if (Rf) atomicAdd(&g_cnt[n][oc][1], Rf);
        }
        if (by == 15) {     // pooled row 127 at lpy==7 -> q 112..127
            int Rl = 0;
#pragma unroll
            for (int j = 28; j < 32; ++j) Rl = __dp4a(row[j], 0x01010101, Rl);
            if (Rl) atomicAdd(&g_cnt[n][oc][2], Rl);
        }
        if (bx == 0) {      // col 0 at lpx==0 -> q = 16*lpy
            int Cf = 0;
#pragma unroll
            for (int j = 0; j < 8; ++j) Cf += spk[oc * 128 + 16 * j];
            if (Cf) atomicAdd(&g_cnt[n][oc][3], Cf);
        }
        if (bx == 7) {      // col 127 at lpx==15 -> q = 16*lpy + 15
            int Cl = 0;
#pragma unroll
            for (int j = 0; j < 8; ++j) Cl += spk[oc * 128 + 16 * j + 15];
            if (Cl) atomicAdd(&g_cnt[n][oc][4], Cl);
        }
        if (by == 0 && bx == 0 && spk[oc * 128 + 0])     g_cnt[n][oc][5] = 1;
        if (by == 0 && bx == 7 && spk[oc * 128 + 15])    g_cnt[n][oc][6] = 1;
        if (by == 15 && bx == 0 && spk[oc * 128 + 112])  g_cnt[n][oc][7] = 1;
        if (by == 15 && bx == 7 && spk[oc * 128 + 127])  g_cnt[n][oc][8] = 1;
    }
}

// ---------------------------------------------------------------------------
// stage B: analytic conv2-mean via T aggregates, BN2, spike -> g_s2
// ---------------------------------------------------------------------------
__global__ __launch_bounds__(256) void stageB_kernel(const float* __restrict__ w2) {
    __shared__ __align__(16) float sT[OC1 * 9];
    const int n = blockIdx.x, tid = threadIdx.x;
    const int lane = tid & 31, warp = tid >> 5;
    if (tid < OC1) {
        const int* c = g_cnt[n][tid];
        int S = c[0], Rf = c[1], Rl = c[2], Cf = c[3], Cl = c[4];
        int Re[3] = {Rl, 0, Rf};
        int Ce[3] = {Cl, 0, Cf};
        int Q[9]  = {c[8], 0, c[7],  0, 0, 0,  c[6], 0, c[5]};
#pragma unroll
        for (int k = 0; k < 9; ++k)
            sT[tid * 9 + k] = (float)(S - Re[k / 3] - Ce[k % 3] + Q[k]);
    }
    __syncthreads();
#pragma unroll 1
    for (int i = 0; i < 16; ++i) {
        const int o = warp * 16 + i;
        const float* wr = w2 + o * 576;
        float acc = 0.f;
#pragma unroll
        for (int t = 0; t < 18; ++t) {
            int j = t * 32 + lane;
            acc = fmaf(__ldg(&wr[j]), sT[j], acc);
        }
#pragma unroll
        for (int s = 16; s; s >>= 1) acc += __shfl_xor_sync(0xffffffffu, acc, s);
        if (lane == 0) {
            float z = acc * (1.f / 16384.f);
            z = z * g_inv2[o] + g_beta2[o];
            g_s2[n][o] = (z > 1.f) ? 1.f : 0.f;
        }
    }
}

// ---------------------------------------------------------------------------
// stage C: feat = |s0 - s1|, fc1+relu, fc2  -> out (32,5)
// ---------------------------------------------------------------------------
__global__ __launch_bounds__(256) void stageC_kernel(const float* __restrict__ fc1w,
                                                     const float* __restrict__ fc1b,
                                                     const float* __restrict__ fc2w,
                                                     const float* __restrict__ fc2b,
                                                     float* __restrict__ out) {
    __shared__ float f[128];
    __shared__ float h[64];
    const int n = blockIdx.x, tid = threadIdx.x;
    const int lane = tid & 31, warp = tid >> 5;
    if (tid < 128) f[tid] = fabsf(g_s2[n][tid] - g_s2[n + 32][tid]);
    __syncthreads();
#pragma unroll 1
    for (int i = 0; i < 8; ++i) {
        const int k = warp * 8 + i;
        const float* wr = fc1w + k * 128;
        float acc = 0.f;
#pragma unroll
        for (int t = 0; t < 4; ++t) {
            int j = t * 32 + lane;
            acc = fmaf(__ldg(&wr[j]), f[j], acc);
        }
#pragma unroll
        for (int s = 16; s; s >>= 1) acc += __shfl_xor_sync(0xffffffffu, acc, s);
        if (lane == 0) h[k] = fmaxf(acc + fc1b[k], 0.f);
    }
    __syncthreads();
    if (warp == 0) {
#pragma unroll 1
        for (int c = 0; c < 5; ++c) {
            const float* wr = fc2w + c * 64;
            float acc = fmaf(__ldg(&wr[lane]), h[lane], 0.f);
            acc = fmaf(__ldg(&wr[lane + 32]), h[lane + 32], acc);
#pragma unroll
            for (int s = 16; s; s >>= 1) acc += __shfl_xor_sync(0xffffffffu, acc, s);
            if (lane == 0) out[n * 5 + c] = acc + fc2b[c];
        }
    }
}

extern "C" void kernel_launch(void* const* d_in, const int* in_sizes, int n_in,
                              void* d_out, int out_size) {
    const float* x0   = (const float*)d_in[0];
    const float* x1   = (const float*)d_in[1];
    const float* w1   = (const float*)d_in[2];
    const float* b1g  = (const float*)d_in[3];
    const float* b1b  = (const float*)d_in[4];
    const float* b1m  = (const float*)d_in[5];
    const float* b1v  = (const float*)d_in[6];
    const float* w2   = (const float*)d_in[7];
    const float* b2g  = (const float*)d_in[8];
    const float* b2b  = (const float*)d_in[9];
    const float* b2m  = (const float*)d_in[10];
    const float* b2v  = (const float*)d_in[11];
    const float* fc1w = (const float*)d_in[12];
    const float* fc1b = (const float*)d_in[13];
    const float* fc2w = (const float*)d_in[14];
    const float* fc2b = (const float*)d_in[15];

    cudaFuncSetAttribute(stageA_kernel,
                         cudaFuncAttributeMaxDynamicSharedMemorySize, SMEM_BYTES);

    prep_kernel<<<32, 256>>>(w1, b1g, b1b, b1m, b1v, b2g, b2b, b2m, b2v);
    dim3 gridA(8, 16, 64);
    stageA_kernel<<<gridA, 128, SMEM_BYTES>>>(x0, x1, w1);
    stageB_kernel<<<64, 256>>>(w2);
    stageC_kernel<<<32, 256>>>(fc1w, fc1b, fc2w, fc2b, (float*)d_out);
}

// round 14
// speedup vs baseline: 1.1661x; 1.1661x over previous
#include <cuda_runtime.h>
#include <cuda_fp16.h>
#include <cstdint>

#define IC1 10
#define OC1 64
#define OC2 128
#define NB  64          // 2 images x 32 batch
#define M0  0.03f       // pre-BN ambiguity margin for fp16 accumulation

__device__ int      g_cnt[NB][OC1][9];   // S, Rf, Rl, Cf, Cl, q_tl, q_tr, q_bl, q_br
__device__ float    g_s2[NB][OC2];
__device__ float    g_inv1[OC1],  g_beta1[OC1];
__device__ float    g_inv2[OC2],  g_beta2[OC2];
__device__ __align__(16) uint16_t g_Wh[90 * 64];  // half weights, [tap][oc]

// dynamic smem layout (bytes)
#define SM_W    0        // half[90*64] = 11520
#define SM_IN   11520    // float[6120] = 24480
#define SM_SPK  36000    // uchar[64*128] = 8192
#define SM_LC   44192    // int[4]
#define SM_LIST 44208    // u16[8192] = 16384 (worst-case exact capacity)
#define SMEM_BYTES 60592

// ---------------------------------------------------------------------------
// nop kernel (launch-slot shims so ncu's 4th-kernel profile lands on stageA)
// ---------------------------------------------------------------------------
__global__ void nop_kernel() {}

// ---------------------------------------------------------------------------
// prep: zero counters, fold BN params, build half weight table [tap][oc]
// ---------------------------------------------------------------------------
__global__ void prep_kernel(const float* __restrict__ w1,
                            const float* __restrict__ g1, const float* __restrict__ b1,
                            const float* __restrict__ m1, const float* __restrict__ v1,
                            const float* __restrict__ g2, const float* __restrict__ b2,
                            const float* __restrict__ m2, const float* __restrict__ v2) {
    int gid = blockIdx.x * blockDim.x + threadIdx.x;
    int* c = &g_cnt[0][0][0];
    for (int i = gid; i < NB * OC1 * 9; i += gridDim.x * blockDim.x) c[i] = 0;
    if (blockIdx.x == 0) {
        int t = threadIdx.x;
        if (t < OC1) {
            float inv = g1[t] / sqrtf(v1[t] + 1e-5f);
            g_inv1[t] = inv;
            g_beta1[t] = b1[t] - m1[t] * inv;
        }
        if (t < OC2) {
            float inv = g2[t] / sqrtf(v2[t] + 1e-5f);
            g_inv2[t] = inv;
            g_beta2[t] = b2[t] - m2[t] * inv;
        }
    }
    if (gid < 90 * 64) {
        int r = gid >> 6, oc = gid & 63;
        __half h = __float2half_rn(__ldg(&w1[oc * 90 + r]));
        g_Wh[r * 64 + oc] = __half_as_ushort(h);
    }
}

// ---------------------------------------------------------------------------
// stage A: conv1 via HFMA2 (position-pair packing; weights broadcast-LDS +
//          PRMT dup) + BN + maxpool2 + margin spike + exact in-block fixup
// grid (8, 16, 64), block 128. Thread = one pooled window for all 64 oc.
// ---------------------------------------------------------------------------
__global__ __launch_bounds__(128, 2) void stageA_kernel(const float* __restrict__ x0,
                                                        const float* __restrict__ x1,
                                                        const float* __restrict__ w1) {
    extern __shared__ char smem[];
    uint16_t*      s_wh  = (uint16_t*)(smem + SM_W);
    float*         s_in  = (float*)(smem + SM_IN);
    unsigned char* spk   = (unsigned char*)(smem + SM_SPK);
    int*           sLC   = (int*)(smem + SM_LC);
    uint16_t*      sList = (uint16_t*)(smem + SM_LIST);

    const int tid = threadIdx.x;
    const int bx = blockIdx.x, by = blockIdx.y, n = blockIdx.z;
    const float* __restrict__ x = (n < 32) ? x0 : x1;
    const int b = n & 31;

    // load half weight table (5760 halves = 720 uint4)
    {
        const uint4* gw = (const uint4*)g_Wh;
        uint4* sw4 = (uint4*)s_wh;
        for (int i = tid; i < 720; i += 128) sw4[i] = __ldg(&gw[i]);
    }
    if (tid == 0) sLC[0] = 0;

    // stage input tile fp32 (18 x 34 per ic), SAME zero padding
    const int iy0 = by * 16 - 1;
    const int ix0 = bx * 32 - 1;
    for (int i = tid; i < IC1 * 612; i += 128) {
        int ic = i / 612, r2 = i % 612;
        int rw = r2 / 34, cl = r2 % 34;
        int gy = iy0 + rw, gx = ix0 + cl;
        float v = 0.f;
        if ((unsigned)gy < 256u && (unsigned)gx < 256u)
            v = __ldg(&x[((b * IC1 + ic) * 256 + gy) * 256 + gx]);
        s_in[i] = v;
    }
    __syncthreads();

    const int lpx = tid & 15, lpy = tid >> 4;
    const int rr = 2 * lpy, cc = 2 * lpx;

    // pack overlapping input pairs once: hp[ic][row 0..3][kx 0..2] = (v[kx], v[kx+1])
    uint32_t hp[IC1 * 12];
#pragma unroll
    for (int ic = 0; ic < IC1; ++ic) {
        float r[4][4];
#pragma unroll
        for (int i = 0; i < 4; ++i) {
            const float2* p = (const float2*)&s_in[ic * 612 + (rr + i) * 34 + cc];
            float2 u = p[0], w = p[1];
            r[i][0] = u.x; r[i][1] = u.y; r[i][2] = w.x; r[i][3] = w.y;
        }
#pragma unroll
        for (int i = 0; i < 4; ++i)
#pragma unroll
            for (int kx = 0; kx < 3; ++kx) {
                __half2 h = __floats2half2_rn(r[i][kx], r[i][kx + 1]);
                hp[ic * 12 + i * 3 + kx] = *reinterpret_cast<uint32_t*>(&h);
            }
    }

    const uint4* s_wh4 = (const uint4*)s_wh;

    // oc-group sweep: 8 oc per g, HFMA2 accumulate (fp16)
#pragma unroll 1
    for (int g = 0; g < 8; ++g) {
        __half2 accA[8], accB[8];   // A: pool row y0 (x0,x1); B: row y1
#pragma unroll
        for (int o = 0; o < 8; ++o) {
            accA[o] = __half2half2(__ushort_as_half(0));
            accB[o] = __half2half2(__ushort_as_half(0));
        }
#pragma unroll
        for (int ic = 0; ic < IC1; ++ic) {
#pragma unroll
            for (int k = 0; k < 9; ++k) {
                const int ky = k / 3, kx = k % 3;
                // one broadcast LDS.128: 8 half weights (ocs g*8 .. g*8+7)
                uint4 wv = s_wh4[(ic * 9 + k) * 8 + g];
                uint32_t wr[4] = {wv.x, wv.y, wv.z, wv.w};
                __half2 hA = *reinterpret_cast<__half2*>(&hp[ic * 12 + ky * 3 + kx]);
                __half2 hB = *reinterpret_cast<__half2*>(&hp[ic * 12 + (ky + 1) * 3 + kx]);
#pragma unroll
                for (int p = 0; p < 4; ++p) {
                    uint32_t dlo = __byte_perm(wr[p], wr[p], 0x1010);  // dup low half
                    uint32_t dhi = __byte_perm(wr[p], wr[p], 0x3232);  // dup high half
                    __half2 w0 = *reinterpret_cast<__half2*>(&dlo);
                    __half2 w1h = *reinterpret_cast<__half2*>(&dhi);
                    accA[2 * p]     = __hfma2(w0,  hA, accA[2 * p]);
                    accB[2 * p]     = __hfma2(w0,  hB, accB[2 * p]);
                    accA[2 * p + 1] = __hfma2(w1h, hA, accA[2 * p + 1]);
                    accB[2 * p + 1] = __hfma2(w1h, hB, accB[2 * p + 1]);
                }
            }
        }
        // epilogue: BN + pool max + margin classify
#pragma unroll
        for (int o = 0; o < 8; ++o) {
            const int oc = g * 8 + o;
            float2 a01 = __half22float2(accA[o]);
            float2 a23 = __half22float2(accB[o]);
            float mx = fmaxf(fmaxf(a01.x, a01.y), fmaxf(a23.x, a23.y));
            float mn = fminf(fminf(a01.x, a01.y), fminf(a23.x, a23.y));
            float inv = __ldg(&g_inv1[oc]);
            float bet = __ldg(&g_beta1[oc]);
            float zb = (inv >= 0.f ? mx : mn) * inv + bet;
            float Mz = M0 * fabsf(inv);
            unsigned char s = 0;
            if (zb - Mz > 1.0f) s = 1;
            else if (zb + Mz > 1.0f) {
                int ix = atomicAdd(&sLC[0], 1);
                sList[ix] = (uint16_t)(tid * 64 + oc);
            }
            spk[oc * 128 + tid] = s;
        }
    }
    __syncthreads();

    // exact fp32 fixup of ambiguous windows from the staged fp32 tile
    {
        const int cnt = sLC[0];
        for (int i = tid; i < cnt; i += 128) {
            const int e = sList[i];
            const int q = e >> 6, oc = e & 63;
            const int r0 = 2 * (q >> 4), c0 = 2 * (q & 15);
            float a0 = 0.f, a1 = 0.f, a2 = 0.f, a3 = 0.f;
#pragma unroll 1
            for (int ic = 0; ic < IC1; ++ic) {
                float v[4][4];
#pragma unroll
                for (int iy = 0; iy < 4; ++iy)
#pragma unroll
                    for (int ixx = 0; ixx < 4; ++ixx)
                        v[iy][ixx] = s_in[ic * 612 + (r0 + iy) * 34 + (c0 + ixx)];
                const float* wr = w1 + oc * 90 + ic * 9;
#pragma unroll
                for (int ky = 0; ky < 3; ++ky)
#pragma unroll
                    for (int kx = 0; kx < 3; ++kx) {
                        float wv = __ldg(&wr[ky * 3 + kx]);
                        a0 = fmaf(wv, v[ky][kx],         a0);
                        a1 = fmaf(wv, v[ky][kx + 1],     a1);
                        a2 = fmaf(wv, v[ky + 1][kx],     a2);
                        a3 = fmaf(wv, v[ky + 1][kx + 1], a3);
                    }
            }
            const float inv = __ldg(&g_inv1[oc]), bet = __ldg(&g_beta1[oc]);
            float zm = fmaxf(fmaxf(fmaf(a0, inv, bet), fmaf(a1, inv, bet)),
                             fmaxf(fmaf(a2, inv, bet), fmaf(a3, inv, bet)));
            spk[oc * 128 + q] = (zm > 1.0f);
        }
    }
    __syncthreads();

    // reduce spike map -> the 9 aggregates
    if (tid < 64) {
        const int oc = tid;
        const int* row = (const int*)&spk[oc * 128];
        int S = 0;
#pragma unroll
        for (int j = 0; j < 32; ++j) S = __dp4a(row[j], 0x01010101, S);
        if (S) atomicAdd(&g_cnt[n][oc][0], S);
        if (by == 0) {      // pooled row 0 lives at lpy==0 -> q 0..15
            int Rf = 0;
#pragma unroll
            for (int j = 0; j < 4; ++j) Rf = __dp4a(row[j], 0x01010101, Rf);
            if (Rf) atomicAdd(&g_cnt[n][oc][1], Rf);
        }
        if (by == 15) {     // pooled row 127 at lpy==7 -> q 112..127
            int Rl = 0;
#pragma unroll
            for (int j = 28; j < 32; ++j) Rl = __dp4a(row[j], 0x01010101, Rl);
            if (Rl) atomicAdd(&g_cnt[n][oc][2], Rl);
        }
        if (bx == 0) {      // col 0 at lpx==0 -> q = 16*lpy
            int Cf = 0;
#pragma unroll
            for (int j = 0; j < 8; ++j) Cf += spk[oc * 128 + 16 * j];
            if (Cf) atomicAdd(&g_cnt[n][oc][3], Cf);
        }
        if (bx == 7) {      // col 127 at lpx==15 -> q = 16*lpy + 15
            int Cl = 0;
#pragma unroll
            for (int j = 0; j < 8; ++j) Cl += spk[oc * 128 + 16 * j + 15];
            if (Cl) atomicAdd(&g_cnt[n][oc][4], Cl);
        }
        if (by == 0 && bx == 0 && spk[oc * 128 + 0])     g_cnt[n][oc][5] = 1;
        if (by == 0 && bx == 7 && spk[oc * 128 + 15])    g_cnt[n][oc][6] = 1;
        if (by == 15 && bx == 0 && spk[oc * 128 + 112])  g_cnt[n][oc][7] = 1;
        if (by == 15 && bx == 7 && spk[oc * 128 + 127])  g_cnt[n][oc][8] = 1;
    }
}

// ---------------------------------------------------------------------------
// stage B: analytic conv2-mean via T aggregates, BN2, spike -> g_s2
// ---------------------------------------------------------------------------
__global__ __launch_bounds__(256) void stageB_kernel(const float* __restrict__ w2) {
    __shared__ __align__(16) float sT[OC1 * 9];
    const int n = blockIdx.x, tid = threadIdx.x;
    const int lane = tid & 31, warp = tid >> 5;
    if (tid < OC1) {
        const int* c = g_cnt[n][tid];
        int S = c[0], Rf = c[1], Rl = c[2], Cf = c[3], Cl = c[4];
        int Re[3] = {Rl, 0, Rf};
        int Ce[3] = {Cl, 0, Cf};
        int Q[9]  = {c[8], 0, c[7],  0, 0, 0,  c[6], 0, c[5]};
#pragma unroll
        for (int k = 0; k < 9; ++k)
            sT[tid * 9 + k] = (float)(S - Re[k / 3] - Ce[k % 3] + Q[k]);
    }
    __syncthreads();
#pragma unroll 1
    for (int i = 0; i < 16; ++i) {
        const int o = warp * 16 + i;
        const float* wr = w2 + o * 576;
        float acc = 0.f;
#pragma unroll
        for (int t = 0; t < 18; ++t) {
            int j = t * 32 + lane;
            acc = fmaf(__ldg(&wr[j]), sT[j], acc);
        }
#pragma unroll
        for (int s = 16; s; s >>= 1) acc += __shfl_xor_sync(0xffffffffu, acc, s);
        if (lane == 0) {
            float z = acc * (1.f / 16384.f);
            z = z * g_inv2[o] + g_beta2[o];
            g_s2[n][o] = (z > 1.f) ? 1.f : 0.f;
        }
    }
}

// ---------------------------------------------------------------------------
// stage C: feat = |s0 - s1|, fc1+relu, fc2  -> out (32,5)
// ---------------------------------------------------------------------------
__global__ __launch_bounds__(256) void stageC_kernel(const float* __restrict__ fc1w,
                                                     const float* __restrict__ fc1b,
                                                     const float* __restrict__ fc2w,
                                                     const float* __restrict__ fc2b,
                                                     float* __restrict__ out) {
    __shared__ float f[128];
    __shared__ float h[64];
    const int n = blockIdx.x, tid = threadIdx.x;
    const int lane = tid & 31, warp = tid >> 5;
    if (tid < 128) f[tid] = fabsf(g_s2[n][tid] - g_s2[n + 32][tid]);
    __syncthreads();
#pragma unroll 1
    for (int i = 0; i < 8; ++i) {
        const int k = warp * 8 + i;
        const float* wr = fc1w + k * 128;
        float acc = 0.f;
#pragma unroll
        for (int t = 0; t < 4; ++t) {
            int j = t * 32 + lane;
            acc = fmaf(__ldg(&wr[j]), f[j], acc);
        }
#pragma unroll
        for (int s = 16; s; s >>= 1) acc += __shfl_xor_sync(0xffffffffu, acc, s);
        if (lane == 0) h[k] = fmaxf(acc + fc1b[k], 0.f);
    }
    __syncthreads();
    if (warp == 0) {
#pragma unroll 1
        for (int c = 0; c < 5; ++c) {
            const float* wr = fc2w + c * 64;
            float acc = fmaf(__ldg(&wr[lane]), h[lane], 0.f);
            acc = fmaf(__ldg(&wr[lane + 32]), h[lane + 32], acc);
#pragma unroll
            for (int s = 16; s; s >>= 1) acc += __shfl_xor_sync(0xffffffffu, acc, s);
            if (lane == 0) out[n * 5 + c] = acc + fc2b[c];
        }
    }
}

extern "C" void kernel_launch(void* const* d_in, const int* in_sizes, int n_in,
                              void* d_out, int out_size) {
    const float* x0   = (const float*)d_in[0];
    const float* x1   = (const float*)d_in[1];
    const float* w1   = (const float*)d_in[2];
    const float* b1g  = (const float*)d_in[3];
    const float* b1b  = (const float*)d_in[4];
    const float* b1m  = (const float*)d_in[5];
    const float* b1v  = (const float*)d_in[6];
    const float* w2   = (const float*)d_in[7];
    const float* b2g  = (const float*)d_in[8];
    const float* b2b  = (const float*)d_in[9];
    const float* b2m  = (const float*)d_in[10];
    const float* b2v  = (const float*)d_in[11];
    const float* fc1w = (const float*)d_in[12];
    const float* fc1b = (const float*)d_in[13];
    const float* fc2w = (const float*)d_in[14];
    const float* fc2b = (const float*)d_in[15];

    cudaFuncSetAttribute(stageA_kernel,
                         cudaFuncAttributeMaxDynamicSharedMemorySize, SMEM_BYTES);

    prep_kernel<<<32, 256>>>(w1, b1g, b1b, b1m, b1v, b2g, b2b, b2m, b2v);
    nop_kernel<<<1, 32>>>();   // shim: put stageA in ncu's profiled (4th) slot
    nop_kernel<<<1, 32>>>();
    dim3 gridA(8, 16, 64);
    stageA_kernel<<<gridA, 128, SMEM_BYTES>>>(x0, x1, w1);
    stageB_kernel<<<64, 256>>>(w2);
    stageC_kernel<<<32, 256>>>(fc1w, fc1b, fc2w, fc2b, (float*)d_out);
}